// round 8
// baseline (speedup 1.0000x reference)
#include <cuda_runtime.h>
#include <math.h>

#define MAX_N    16
#define NBINS    4096
#define CAND_MAX 16384
#define HT       1024
#define BPB      18
#define RB       32

__device__ unsigned int       g_hist[MAX_N * NBINS];
__device__ int                g_count[MAX_N];
__device__ int                g_T[MAX_N];
__device__ int                g_fbflag[MAX_N];
__device__ unsigned int       g_done[MAX_N];
__device__ int                g_rank[MAX_N * CAND_MAX];
__device__ unsigned long long g_cand[MAX_N * CAND_MAX];

__device__ __forceinline__ unsigned int mono_f32(float f) {
    unsigned int u = __float_as_uint(f);
    return (u & 0x80000000u) ? ~u : (u | 0x80000000u);
}
__device__ __forceinline__ float inv_mono(unsigned int m) {
    unsigned int u = (m & 0x80000000u) ? (m & 0x7FFFFFFFu) : ~m;
    return __uint_as_float(u);
}

// Suffix-scan threshold finder over a 4096-bin histogram. blockDim must be 1024;
// thread t owns bins [4t, 4t+4). Finds largest bin with suffix >= st.
// Exactly one thread writes *out. 2 __syncthreads total.
__device__ __forceinline__ void suffix_threshold(unsigned int h0, unsigned int h1,
                                                 unsigned int h2, unsigned int h3,
                                                 unsigned int st,
                                                 unsigned int* warp_tot, int* out) {
    const int t = threadIdx.x, lane = t & 31, wid = t >> 5;
    unsigned int seg = h0 + h1 + h2 + h3;
    unsigned int suf = seg;
#pragma unroll
    for (int d = 1; d < 32; d <<= 1) {
        unsigned int v = __shfl_down_sync(0xFFFFFFFFu, suf, d);
        if (lane + d < 32) suf += v;
    }
    if (lane == 0) warp_tot[wid] = suf;
    __syncthreads();
    if (wid == 0) {
        unsigned int wv = warp_tot[lane];
        unsigned int wsuf = wv;
#pragma unroll
        for (int d = 1; d < 32; d <<= 1) {
            unsigned int v = __shfl_down_sync(0xFFFFFFFFu, wsuf, d);
            if (lane + d < 32) wsuf += v;
        }
        warp_tot[lane] = wsuf - wv;   // sum over warps strictly above
    }
    __syncthreads();
    unsigned int S  = suf + warp_tot[wid];   // suffix from bin 4t
    unsigned int sN = S - seg;               // suffix from bin 4(t+1)
    unsigned int s3 = sN + h3;
    unsigned int s2 = s3 + h2;
    unsigned int s1 = s2 + h1;
    unsigned int s0 = S;
    if      (s3 >= st && sN < st) *out = t * 4 + 3;
    else if (s2 >= st && s3 < st) *out = t * 4 + 2;
    else if (s1 >= st && s2 < st) *out = t * 4 + 1;
    else if (s0 >= st && s1 < st) *out = t * 4 + 0;
}

// ---------------------------------------------------------------------------
// Pass 1: sampled threshold (1 block/batch). 4096 float4 = 16384 samples,
// strided over the WHOLE batch. Also zeroes all per-replay state.
// grid N x 1024
// ---------------------------------------------------------------------------
__global__ void __launch_bounds__(1024) sample_thresh_kernel(
        const float* __restrict__ scores, int A, int k) {
    __shared__ unsigned int sh[NBINS];
    __shared__ unsigned int warp_tot[32];
    __shared__ int sT;
    const int b = blockIdx.x;
    const int t = threadIdx.x;

    for (int i = t; i < NBINS; i += 1024) { sh[i] = 0; g_hist[b * NBINS + i] = 0; }
    for (int i = t; i < CAND_MAX; i += 1024) g_rank[b * CAND_MAX + i] = 0;
    if (t == 0) { g_count[b] = 0; g_fbflag[b] = 0; }
    __syncthreads();

    const size_t base = (size_t)b * (size_t)A;
    const int A4 = A >> 2;
    long long nsamp;
    if ((A & 3) == 0 && A4 >= 4096) {
        const float4* s4 = (const float4*)(scores + base);
#pragma unroll
        for (int r = 0; r < 4; r++) {
            int j = t + r * 1024;                          // j in [0, 4096)
            size_t pos = ((size_t)j * (size_t)A4) >> 12;   // j*A4/4096, in [0, A4)
            float4 v = s4[pos];
            atomicAdd(&sh[mono_f32(v.x) >> 20], 1u);
            atomicAdd(&sh[mono_f32(v.y) >> 20], 1u);
            atomicAdd(&sh[mono_f32(v.z) >> 20], 1u);
            atomicAdd(&sh[mono_f32(v.w) >> 20], 1u);
        }
        nsamp = 4096 * 4;                                  // 16384 samples
    } else {
        nsamp = A;   // small A: exact histogram of everything
        for (int i = t; i < A; i += 1024)
            atomicAdd(&sh[mono_f32(scores[base + i]) >> 20], 1u);
    }
    __syncthreads();

    unsigned int st;
    if (nsamp == A) {
        st = (unsigned)min(k, A);   // exact threshold
    } else {
        long long tgt = (nsamp * (3LL * k)) / (long long)A;  // target ~3k candidates
        if (tgt < 1) tgt = 1;
        if (tgt > nsamp) tgt = nsamp;
        st = (unsigned)tgt;
    }

    suffix_threshold(sh[t * 4], sh[t * 4 + 1], sh[t * 4 + 2], sh[t * 4 + 3],
                     st, warp_tot, &sT);
    __syncthreads();
    if (t == 0) g_T[b] = sT;
}

// ---------------------------------------------------------------------------
// warp-aggregated candidate push (whole warp must execute; pred per-lane)
// ---------------------------------------------------------------------------
__device__ __forceinline__ void push_warp(int b, bool pred, unsigned long long key) {
    unsigned int bal = __ballot_sync(0xFFFFFFFFu, pred);
    if (!bal) return;
    const int lane = threadIdx.x & 31;
    const int leader = __ffs(bal) - 1;
    int base = 0;
    if (lane == leader) base = atomicAdd(&g_count[b], __popc(bal));
    base = __shfl_sync(0xFFFFFFFFu, base, leader);
    if (pred) {
        int pos = base + __popc(bal & ((1u << lane) - 1u));
        if (pos < CAND_MAX) g_cand[b * CAND_MAX + pos] = key;
    }
}

// ---------------------------------------------------------------------------
// Pass 2: the single full sweep — compact everything with bin >= T.
// grid (BPB, N) x HT (warp-uniform iteration for safe ballots)
// ---------------------------------------------------------------------------
__global__ void __launch_bounds__(HT) compact_kernel(
        const float* __restrict__ scores, int A) {
    const int b = blockIdx.y;
    const int T = g_T[b];
    const size_t base = (size_t)b * (size_t)A;
    const int lane = threadIdx.x & 31;

    if ((A & 3) == 0) {
        const float4* s4 = (const float4*)(scores + base);
        const int A4 = A >> 2;
        const int warp0 = blockIdx.x * (HT / 32) + (threadIdx.x >> 5);
        for (int i0 = warp0 * 32; i0 < A4; i0 += BPB * HT) {
            const int i = i0 + lane;
            const bool in = i < A4;
            float4 v;
            if (in) v = s4[i];
            unsigned int o = (unsigned)(i << 2);
            unsigned int mx = in ? mono_f32(v.x) : 0u;
            unsigned int my = in ? mono_f32(v.y) : 0u;
            unsigned int mz = in ? mono_f32(v.z) : 0u;
            unsigned int mw = in ? mono_f32(v.w) : 0u;
            push_warp(b, in && (int)(mx >> 20) >= T,
                      ((unsigned long long)mx << 32) | (0xFFFFFFFFu - (o + 0u)));
            push_warp(b, in && (int)(my >> 20) >= T,
                      ((unsigned long long)my << 32) | (0xFFFFFFFFu - (o + 1u)));
            push_warp(b, in && (int)(mz >> 20) >= T,
                      ((unsigned long long)mz << 32) | (0xFFFFFFFFu - (o + 2u)));
            push_warp(b, in && (int)(mw >> 20) >= T,
                      ((unsigned long long)mw << 32) | (0xFFFFFFFFu - (o + 3u)));
        }
    } else {
        const int warp0 = blockIdx.x * (HT / 32) + (threadIdx.x >> 5);
        for (int i0 = warp0 * 32; i0 < A; i0 += BPB * HT) {
            const int i = i0 + lane;
            const bool in = i < A;
            unsigned int m = in ? mono_f32(scores[base + i]) : 0u;
            push_warp(b, in && (int)(m >> 20) >= T,
                      ((unsigned long long)m << 32) | (0xFFFFFFFFu - (unsigned)i));
        }
    }
}

// ---------------------------------------------------------------------------
// Pass 3 (guarded fallback, ~never runs): exact histogram sweep + threshold.
// grid (BPB, N) x 1024
// ---------------------------------------------------------------------------
__global__ void __launch_bounds__(1024) fb_hist_kernel(
        const float* __restrict__ scores, int A, int k) {
    const int b = blockIdx.y;
    {
        const int c = g_count[b];
        if (c >= min(k, A) && c <= CAND_MAX) return;   // sampled path succeeded
    }
    __shared__ unsigned int sh[NBINS];
    __shared__ unsigned int warp_tot[32];
    __shared__ int sT;
    __shared__ bool s_last;
    const int t = threadIdx.x;

    for (int i = t; i < NBINS; i += 1024) sh[i] = 0;
    __syncthreads();
    const size_t base = (size_t)b * (size_t)A;
    for (int i = blockIdx.x * 1024 + t; i < A; i += BPB * 1024)
        atomicAdd(&sh[mono_f32(scores[base + i]) >> 20], 1u);
    __syncthreads();
    for (int i = t; i < NBINS; i += 1024) {
        unsigned int c = sh[i];
        if (c) atomicAdd(&g_hist[b * NBINS + i], c);
    }
    __threadfence();
    __syncthreads();
    if (t == 0) s_last = (atomicAdd(&g_done[b], 1u) == (unsigned)gridDim.x - 1u);
    __syncthreads();
    if (!s_last) return;
    if (t == 0) g_done[b] = 0;

    unsigned int h0 = g_hist[b * NBINS + t * 4];
    unsigned int h1 = g_hist[b * NBINS + t * 4 + 1];
    unsigned int h2 = g_hist[b * NBINS + t * 4 + 2];
    unsigned int h3 = g_hist[b * NBINS + t * 4 + 3];
    suffix_threshold(h0, h1, h2, h3, (unsigned)min(k, A), warp_tot, &sT);
    __syncthreads();
    if (t == 0) { g_T[b] = sT; g_count[b] = 0; g_fbflag[b] = 1; }
}

// ---------------------------------------------------------------------------
// Pass 4 (guarded fallback): recompact with exact threshold.
// grid (BPB, N) x HT
// ---------------------------------------------------------------------------
__global__ void __launch_bounds__(HT) fb_compact_kernel(
        const float* __restrict__ scores, int A) {
    const int b = blockIdx.y;
    if (!g_fbflag[b]) return;
    const int T = g_T[b];
    const size_t base = (size_t)b * (size_t)A;
    for (int i = blockIdx.x * HT + threadIdx.x; i < A; i += BPB * HT) {
        unsigned int m = mono_f32(scores[base + i]);
        if ((int)(m >> 20) >= T) {
            int p = atomicAdd(&g_count[b], 1);
            if (p < CAND_MAX)
                g_cand[b * CAND_MAX + p] =
                    ((unsigned long long)m << 32) |
                    (unsigned long long)(0xFFFFFFFFu - (unsigned)i);
        }
    }
}

// ---------------------------------------------------------------------------
// Pass 5: rank counting. grid (RB, N) x 1024
// ---------------------------------------------------------------------------
__global__ void __launch_bounds__(1024) rank_kernel() {
    __shared__ unsigned long long ck[CAND_MAX / RB];   // 512
    const int b = blockIdx.y;
    const int t = threadIdx.x;
    const int Ct = min(g_count[b], CAND_MAX);
    const int chunk = (Ct + RB - 1) / RB;
    const int begin = blockIdx.x * chunk;
    int len = Ct - begin;
    if (len > chunk) len = chunk;
    if (len <= 0) return;

    for (int j = t; j < len; j += 1024)
        ck[j] = g_cand[b * CAND_MAX + begin + j];
    __syncthreads();

    const unsigned long long* cand = &g_cand[b * CAND_MAX];
    int* rank = &g_rank[b * CAND_MAX];
    for (int bi = 0; bi < Ct; bi += 4096) {
        const int i0 = bi + t, i1 = i0 + 1024, i2 = i0 + 2048, i3 = i0 + 3072;
        unsigned long long m0 = ~0ull, m1 = ~0ull, m2 = ~0ull, m3 = ~0ull;
        if (i0 < Ct) m0 = cand[i0];
        if (i1 < Ct) m1 = cand[i1];
        if (i2 < Ct) m2 = cand[i2];
        if (i3 < Ct) m3 = cand[i3];
        int c0 = 0, c1 = 0, c2 = 0, c3 = 0;
        for (int j = 0; j < len; j++) {
            unsigned long long kj = ck[j];
            c0 += (kj > m0);
            c1 += (kj > m1);
            c2 += (kj > m2);
            c3 += (kj > m3);
        }
        if (i0 < Ct && c0) atomicAdd(&rank[i0], c0);
        if (i1 < Ct && c1) atomicAdd(&rank[i1], c1);
        if (i2 < Ct && c2) atomicAdd(&rank[i2], c2);
        if (i3 < Ct && c3) atomicAdd(&rank[i3], c3);
    }
}

// ---------------------------------------------------------------------------
// Pass 6: decode + scatter by rank. grid (CAND_MAX/1024, N) x 1024
// ---------------------------------------------------------------------------
__global__ void __launch_bounds__(1024) decode_kernel(
        const float* __restrict__ anchors,
        const float* __restrict__ breg,
        float* __restrict__ out,
        int A, int k) {
    const int b = blockIdx.y;
    const int i = blockIdx.x * 1024 + threadIdx.x;
    if (i >= min(g_count[b], CAND_MAX)) return;
    const int r = g_rank[b * CAND_MAX + i];
    if (r >= k) return;

    const unsigned long long key = g_cand[b * CAND_MAX + i];
    const float CLIP = 4.135166556742356f;   // log(1000/16)
    const size_t base = (size_t)b * (size_t)A;
    unsigned int idx = 0xFFFFFFFFu - (unsigned int)(key & 0xFFFFFFFFull);
    float sc = inv_mono((unsigned int)(key >> 32));
    size_t g4 = (base + (size_t)idx) * 4;

    float4 box = *(const float4*)(anchors + g4);
    float4 rc  = *(const float4*)(breg + g4);

    float w  = box.z - box.x + 1.0f;
    float h  = box.w - box.y + 1.0f;
    float cx = box.x + 0.5f * w;
    float cy = box.y + 0.5f * h;

    float dw = fminf(rc.z, CLIP);
    float dh = fminf(rc.w, CLIP);

    float pcx = rc.x * w + cx;
    float pcy = rc.y * h + cy;
    float pw  = expf(dw) * w;
    float ph  = expf(dh) * h;

    float* o = out + ((size_t)b * k + r) * 5;
    o[0] = pcx - 0.5f * pw;
    o[1] = pcy - 0.5f * ph;
    o[2] = pcx + 0.5f * pw - 1.0f;
    o[3] = pcy + 0.5f * ph - 1.0f;
    o[4] = sc;
}

// ---------------------------------------------------------------------------
extern "C" void kernel_launch(void* const* d_in, const int* in_sizes, int n_in,
                              void* d_out, int out_size) {
    const float* anchors    = (const float*)d_in[0];
    const float* objectness = (const float*)d_in[1];
    const float* breg       = (const float*)d_in[2];
    float* out = (float*)d_out;

    const int NA = in_sizes[1];
    const int k  = 2000;
    const int N  = out_size / (k * 5);
    const int A  = NA / N;

    sample_thresh_kernel<<<N, 1024>>>(objectness, A, k);
    compact_kernel<<<dim3(BPB, N), HT>>>(objectness, A);
    fb_hist_kernel<<<dim3(BPB, N), 1024>>>(objectness, A, k);
    fb_compact_kernel<<<dim3(BPB, N), HT>>>(objectness, A);
    rank_kernel<<<dim3(RB, N), 1024>>>();
    decode_kernel<<<dim3(CAND_MAX / 1024, N), 1024>>>(anchors, breg, out, A, k);
}

// round 9
// speedup vs baseline: 3.7362x; 3.7362x over previous
#include <cuda_runtime.h>
#include <math.h>

#define MAX_N    16
#define NBINS    4096
#define CAND_MAX 16384
#define HT       1024
#define BPB      18
#define RB       32

__device__ unsigned int       g_hist[MAX_N * NBINS];
__device__ int                g_count[MAX_N];
__device__ unsigned int       g_T24[MAX_N];     // 24-bit key-prefix threshold
__device__ int                g_fbflag[MAX_N];
__device__ unsigned int       g_done[MAX_N];
__device__ int                g_rank[MAX_N * CAND_MAX];
__device__ unsigned long long g_cand[MAX_N * CAND_MAX];

__device__ __forceinline__ unsigned int mono_f32(float f) {
    unsigned int u = __float_as_uint(f);
    return (u & 0x80000000u) ? ~u : (u | 0x80000000u);
}
__device__ __forceinline__ float inv_mono(unsigned int m) {
    unsigned int u = (m & 0x80000000u) ? (m & 0x7FFFFFFFu) : ~m;
    return __uint_as_float(u);
}

// Suffix-scan threshold over 4096-bin hist in sh[]. blockDim = 1024; thread t
// owns bins [4t,4t+4). Finds largest bin with suffix >= st; writes bin to *out
// and the suffix strictly above that bin to *outAbove (single writer).
__device__ __forceinline__ void suffix_threshold(const unsigned int* sh,
                                                 unsigned int st,
                                                 unsigned int* warp_tot,
                                                 int* out, unsigned int* outAbove) {
    const int t = threadIdx.x, lane = t & 31, wid = t >> 5;
    unsigned int h0 = sh[t * 4], h1 = sh[t * 4 + 1], h2 = sh[t * 4 + 2], h3 = sh[t * 4 + 3];
    unsigned int seg = h0 + h1 + h2 + h3;
    unsigned int suf = seg;
#pragma unroll
    for (int d = 1; d < 32; d <<= 1) {
        unsigned int v = __shfl_down_sync(0xFFFFFFFFu, suf, d);
        if (lane + d < 32) suf += v;
    }
    if (lane == 0) warp_tot[wid] = suf;
    __syncthreads();
    if (wid == 0) {
        unsigned int wv = warp_tot[lane];
        unsigned int wsuf = wv;
#pragma unroll
        for (int d = 1; d < 32; d <<= 1) {
            unsigned int v = __shfl_down_sync(0xFFFFFFFFu, wsuf, d);
            if (lane + d < 32) wsuf += v;
        }
        warp_tot[lane] = wsuf - wv;   // strictly-after-warp suffix
    }
    __syncthreads();
    unsigned int S  = suf + warp_tot[wid];
    unsigned int sN = S - seg;
    unsigned int s3 = sN + h3;
    unsigned int s2 = s3 + h2;
    unsigned int s1 = s2 + h1;
    unsigned int s0 = S;
    if      (s3 >= st && sN < st) { *out = t * 4 + 3; *outAbove = sN; }
    else if (s2 >= st && s3 < st) { *out = t * 4 + 2; *outAbove = s3; }
    else if (s1 >= st && s2 < st) { *out = t * 4 + 1; *outAbove = s2; }
    else if (s0 >= st && s1 < st) { *out = t * 4 + 0; *outAbove = s1; }
}

// ---------------------------------------------------------------------------
// Pass 1: 24-bit sampled threshold (1 block/batch). 16384 samples, two-level:
// 12-bit coarse + 12-bit sub-bin refine on the same register-held samples.
// Also zeroes all per-replay state. grid N x 1024
// ---------------------------------------------------------------------------
__global__ void __launch_bounds__(1024) sample_thresh_kernel(
        const float* __restrict__ scores, int A, int k) {
    __shared__ unsigned int sh[NBINS];
    __shared__ unsigned int warp_tot[32];
    __shared__ int sT1, sT2;
    __shared__ unsigned int sS1, sDummy;
    const int b = blockIdx.x;
    const int t = threadIdx.x;

    for (int i = t; i < NBINS; i += 1024) { sh[i] = 0; g_hist[b * NBINS + i] = 0; }
    for (int i = t; i < CAND_MAX; i += 1024) g_rank[b * CAND_MAX + i] = 0;
    if (t == 0) { g_count[b] = 0; g_fbflag[b] = 0; }
    __syncthreads();

    const size_t base = (size_t)b * (size_t)A;
    const int A4 = A >> 2;

    if ((A & 3) == 0 && A4 >= 4096) {
        const float4* s4 = (const float4*)(scores + base);
        unsigned int m[16];
#pragma unroll
        for (int r = 0; r < 4; r++) {
            int j = t + r * 1024;                          // j in [0, 4096)
            size_t pos = ((size_t)j * (size_t)A4) >> 12;   // strided over full batch
            float4 v = s4[pos];
            m[r * 4 + 0] = mono_f32(v.x);
            m[r * 4 + 1] = mono_f32(v.y);
            m[r * 4 + 2] = mono_f32(v.z);
            m[r * 4 + 3] = mono_f32(v.w);
        }
#pragma unroll
        for (int q = 0; q < 16; q++) atomicAdd(&sh[m[q] >> 20], 1u);
        __syncthreads();

        // target ~3500 candidates: st = 16384 * (7k/4) / A
        long long tgt = (16384LL * 7LL * (long long)k) / (4LL * (long long)A);
        if (tgt < 1) tgt = 1;
        if (tgt > 16384) tgt = 16384;
        const unsigned int st = (unsigned)tgt;

        suffix_threshold(sh, st, warp_tot, &sT1, &sS1);
        __syncthreads();
        const int T1 = sT1;
        const unsigned int S1 = sS1;        // sampled count strictly above bin T1
        __syncthreads();

        // level 2: histogram bits [8,20) of samples inside bin T1
        for (int i = t; i < NBINS; i += 1024) sh[i] = 0;
        __syncthreads();
#pragma unroll
        for (int q = 0; q < 16; q++)
            if ((int)(m[q] >> 20) == T1) atomicAdd(&sh[(m[q] >> 8) & 0xFFFu], 1u);
        __syncthreads();

        unsigned int st2 = st - S1;         // >= 1 by construction
        suffix_threshold(sh, st2, warp_tot, &sT2, &sDummy);
        __syncthreads();
        if (t == 0) g_T24[b] = ((unsigned)T1 << 12) | (unsigned)sT2;
    } else {
        // small/odd A: exact 12-bit histogram of everything
        for (int i = t; i < A; i += 1024)
            atomicAdd(&sh[mono_f32(scores[base + i]) >> 20], 1u);
        __syncthreads();
        suffix_threshold(sh, (unsigned)min(k, A), warp_tot, &sT1, &sS1);
        __syncthreads();
        if (t == 0) g_T24[b] = (unsigned)sT1 << 12;   // exact; count >= min(k,A)
    }
}

// ---------------------------------------------------------------------------
// warp-aggregated candidate push (whole warp must execute; pred per-lane)
// ---------------------------------------------------------------------------
__device__ __forceinline__ void push_warp(int b, bool pred, unsigned long long key) {
    unsigned int bal = __ballot_sync(0xFFFFFFFFu, pred);
    if (!bal) return;
    const int lane = threadIdx.x & 31;
    const int leader = __ffs(bal) - 1;
    int base = 0;
    if (lane == leader) base = atomicAdd(&g_count[b], __popc(bal));
    base = __shfl_sync(0xFFFFFFFFu, base, leader);
    if (pred) {
        int pos = base + __popc(bal & ((1u << lane) - 1u));
        if (pos < CAND_MAX) g_cand[b * CAND_MAX + pos] = key;
    }
}

// ---------------------------------------------------------------------------
// Pass 2: the single full sweep — compact (m>>8) >= T24.
// grid (BPB, N) x HT (warp-uniform iteration for safe ballots)
// ---------------------------------------------------------------------------
__global__ void __launch_bounds__(HT) compact_kernel(
        const float* __restrict__ scores, int A) {
    const int b = blockIdx.y;
    const unsigned int T24 = g_T24[b];
    const size_t base = (size_t)b * (size_t)A;
    const int lane = threadIdx.x & 31;

    if ((A & 3) == 0) {
        const float4* s4 = (const float4*)(scores + base);
        const int A4 = A >> 2;
        const int warp0 = blockIdx.x * (HT / 32) + (threadIdx.x >> 5);
        for (int i0 = warp0 * 32; i0 < A4; i0 += BPB * HT) {
            const int i = i0 + lane;
            const bool in = i < A4;
            float4 v;
            if (in) v = s4[i];
            unsigned int o = (unsigned)(i << 2);
            unsigned int mx = in ? mono_f32(v.x) : 0u;
            unsigned int my = in ? mono_f32(v.y) : 0u;
            unsigned int mz = in ? mono_f32(v.z) : 0u;
            unsigned int mw = in ? mono_f32(v.w) : 0u;
            push_warp(b, in && (mx >> 8) >= T24,
                      ((unsigned long long)mx << 32) | (0xFFFFFFFFu - (o + 0u)));
            push_warp(b, in && (my >> 8) >= T24,
                      ((unsigned long long)my << 32) | (0xFFFFFFFFu - (o + 1u)));
            push_warp(b, in && (mz >> 8) >= T24,
                      ((unsigned long long)mz << 32) | (0xFFFFFFFFu - (o + 2u)));
            push_warp(b, in && (mw >> 8) >= T24,
                      ((unsigned long long)mw << 32) | (0xFFFFFFFFu - (o + 3u)));
        }
    } else {
        const int warp0 = blockIdx.x * (HT / 32) + (threadIdx.x >> 5);
        for (int i0 = warp0 * 32; i0 < A; i0 += BPB * HT) {
            const int i = i0 + lane;
            const bool in = i < A;
            unsigned int m = in ? mono_f32(scores[base + i]) : 0u;
            push_warp(b, in && (m >> 8) >= T24,
                      ((unsigned long long)m << 32) | (0xFFFFFFFFu - (unsigned)i));
        }
    }
}

// ---------------------------------------------------------------------------
// Pass 3 (guarded fallback, ~never runs): exact 12-bit hist + threshold.
// grid (BPB, N) x 1024
// ---------------------------------------------------------------------------
__global__ void __launch_bounds__(1024) fb_hist_kernel(
        const float* __restrict__ scores, int A, int k) {
    const int b = blockIdx.y;
    {
        const int c = g_count[b];
        if (c >= min(k, A) && c <= CAND_MAX) return;   // sampled path succeeded
    }
    __shared__ unsigned int sh[NBINS];
    __shared__ unsigned int warp_tot[32];
    __shared__ int sT;
    __shared__ unsigned int sAb;
    __shared__ bool s_last;
    const int t = threadIdx.x;

    for (int i = t; i < NBINS; i += 1024) sh[i] = 0;
    __syncthreads();
    const size_t base = (size_t)b * (size_t)A;
    for (int i = blockIdx.x * 1024 + t; i < A; i += BPB * 1024)
        atomicAdd(&sh[mono_f32(scores[base + i]) >> 20], 1u);
    __syncthreads();
    for (int i = t; i < NBINS; i += 1024) {
        unsigned int c = sh[i];
        if (c) atomicAdd(&g_hist[b * NBINS + i], c);
    }
    __threadfence();
    __syncthreads();
    if (t == 0) s_last = (atomicAdd(&g_done[b], 1u) == (unsigned)gridDim.x - 1u);
    __syncthreads();
    if (!s_last) return;
    if (t == 0) g_done[b] = 0;

    for (int i = t; i < NBINS; i += 1024) sh[i] = g_hist[b * NBINS + i];
    __syncthreads();
    suffix_threshold(sh, (unsigned)min(k, A), warp_tot, &sT, &sAb);
    __syncthreads();
    if (t == 0) { g_T24[b] = (unsigned)sT << 12; g_count[b] = 0; g_fbflag[b] = 1; }
}

// ---------------------------------------------------------------------------
// Pass 4 (guarded fallback): recompact with exact threshold. grid (BPB,N) x HT
// ---------------------------------------------------------------------------
__global__ void __launch_bounds__(HT) fb_compact_kernel(
        const float* __restrict__ scores, int A) {
    const int b = blockIdx.y;
    if (!g_fbflag[b]) return;
    const unsigned int T24 = g_T24[b];
    const size_t base = (size_t)b * (size_t)A;
    for (int i = blockIdx.x * HT + threadIdx.x; i < A; i += BPB * HT) {
        unsigned int m = mono_f32(scores[base + i]);
        if ((m >> 8) >= T24) {
            int p = atomicAdd(&g_count[b], 1);
            if (p < CAND_MAX)
                g_cand[b * CAND_MAX + p] =
                    ((unsigned long long)m << 32) |
                    (unsigned long long)(0xFFFFFFFFu - (unsigned)i);
        }
    }
}

// ---------------------------------------------------------------------------
// Pass 5: rank counting. grid (RB, N) x 1024
// ---------------------------------------------------------------------------
__global__ void __launch_bounds__(1024) rank_kernel() {
    __shared__ unsigned long long ck[CAND_MAX / RB];   // 512
    const int b = blockIdx.y;
    const int t = threadIdx.x;
    const int Ct = min(g_count[b], CAND_MAX);
    const int chunk = (Ct + RB - 1) / RB;
    const int begin = blockIdx.x * chunk;
    int len = Ct - begin;
    if (len > chunk) len = chunk;
    if (len <= 0) return;

    for (int j = t; j < len; j += 1024)
        ck[j] = g_cand[b * CAND_MAX + begin + j];
    __syncthreads();

    const unsigned long long* cand = &g_cand[b * CAND_MAX];
    int* rank = &g_rank[b * CAND_MAX];
    for (int bi = 0; bi < Ct; bi += 4096) {
        const int i0 = bi + t, i1 = i0 + 1024, i2 = i0 + 2048, i3 = i0 + 3072;
        unsigned long long m0 = ~0ull, m1 = ~0ull, m2 = ~0ull, m3 = ~0ull;
        if (i0 < Ct) m0 = cand[i0];
        if (i1 < Ct) m1 = cand[i1];
        if (i2 < Ct) m2 = cand[i2];
        if (i3 < Ct) m3 = cand[i3];
        int c0 = 0, c1 = 0, c2 = 0, c3 = 0;
        for (int j = 0; j < len; j++) {
            unsigned long long kj = ck[j];
            c0 += (kj > m0);
            c1 += (kj > m1);
            c2 += (kj > m2);
            c3 += (kj > m3);
        }
        if (i0 < Ct && c0) atomicAdd(&rank[i0], c0);
        if (i1 < Ct && c1) atomicAdd(&rank[i1], c1);
        if (i2 < Ct && c2) atomicAdd(&rank[i2], c2);
        if (i3 < Ct && c3) atomicAdd(&rank[i3], c3);
    }
}

// ---------------------------------------------------------------------------
// Pass 6: decode + scatter by rank. grid (CAND_MAX/1024, N) x 1024
// ---------------------------------------------------------------------------
__global__ void __launch_bounds__(1024) decode_kernel(
        const float* __restrict__ anchors,
        const float* __restrict__ breg,
        float* __restrict__ out,
        int A, int k) {
    const int b = blockIdx.y;
    const int i = blockIdx.x * 1024 + threadIdx.x;
    if (i >= min(g_count[b], CAND_MAX)) return;
    const int r = g_rank[b * CAND_MAX + i];
    if (r >= k) return;

    const unsigned long long key = g_cand[b * CAND_MAX + i];
    const float CLIP = 4.135166556742356f;   // log(1000/16)
    const size_t base = (size_t)b * (size_t)A;
    unsigned int idx = 0xFFFFFFFFu - (unsigned int)(key & 0xFFFFFFFFull);
    float sc = inv_mono((unsigned int)(key >> 32));
    size_t g4 = (base + (size_t)idx) * 4;

    float4 box = *(const float4*)(anchors + g4);
    float4 rc  = *(const float4*)(breg + g4);

    float w  = box.z - box.x + 1.0f;
    float h  = box.w - box.y + 1.0f;
    float cx = box.x + 0.5f * w;
    float cy = box.y + 0.5f * h;

    float dw = fminf(rc.z, CLIP);
    float dh = fminf(rc.w, CLIP);

    float pcx = rc.x * w + cx;
    float pcy = rc.y * h + cy;
    float pw  = expf(dw) * w;
    float ph  = expf(dh) * h;

    float* o = out + ((size_t)b * k + r) * 5;
    o[0] = pcx - 0.5f * pw;
    o[1] = pcy - 0.5f * ph;
    o[2] = pcx + 0.5f * pw - 1.0f;
    o[3] = pcy + 0.5f * ph - 1.0f;
    o[4] = sc;
}

// ---------------------------------------------------------------------------
extern "C" void kernel_launch(void* const* d_in, const int* in_sizes, int n_in,
                              void* d_out, int out_size) {
    const float* anchors    = (const float*)d_in[0];
    const float* objectness = (const float*)d_in[1];
    const float* breg       = (const float*)d_in[2];
    float* out = (float*)d_out;

    const int NA = in_sizes[1];
    const int k  = 2000;
    const int N  = out_size / (k * 5);
    const int A  = NA / N;

    sample_thresh_kernel<<<N, 1024>>>(objectness, A, k);
    compact_kernel<<<dim3(BPB, N), HT>>>(objectness, A);
    fb_hist_kernel<<<dim3(BPB, N), 1024>>>(objectness, A, k);
    fb_compact_kernel<<<dim3(BPB, N), HT>>>(objectness, A);
    rank_kernel<<<dim3(RB, N), 1024>>>();
    decode_kernel<<<dim3(CAND_MAX / 1024, N), 1024>>>(anchors, breg, out, A, k);
}